// round 7
// baseline (speedup 1.0000x reference)
#include <cuda_runtime.h>
#include <cuda_bf16.h>
#include <math.h>
#include <stdint.h>

#define BATCH   2
#define SEQ     2048
#define DMODEL  2048
#define NHEADS  32
#define DSTATE  64
#define HEADDIM 64
#define DCONV   4
#define INTERSZ 5504
#define DINNER  DMODEL
#define CONVDIM (DINNER + 2*NHEADS*DSTATE)              /* 6144 */
#define DPROJ   (2*DINNER + 2*NHEADS*DSTATE + NHEADS)   /* 8224 */
#define MROWS   (BATCH*SEQ)                             /* 4096 */

// ---------------- scratch ----------------
__device__ float g_xnorm[(size_t)MROWS * DMODEL];
__device__ float g_zx   [(size_t)MROWS * DPROJ];
__device__ float g_xbc  [(size_t)MROWS * CONVDIM];
__device__ float g_gated[(size_t)MROWS * DMODEL];
__device__ float g_res2 [(size_t)MROWS * DMODEL];
__device__ float g_guf  [(size_t)MROWS * 11008];
// packed bf16 hi/lo tile chunks: chunk = 128 rows x 16 cols, 48B rows,
// hi plane 6144B then lo plane 6144B => 12288B per (tile,slab16).
__device__ __align__(128) uint8_t g_pa[(size_t)32 * 344 * 12288];  /* 135 MB */
__device__ __align__(128) uint8_t g_pb[(size_t)86 * 128 * 12288];  /* 135 MB */

static __device__ __forceinline__ uint32_t smem_u32(const void* p) {
    uint32_t a;
    asm("{ .reg .u64 t; cvta.to.shared.u64 t, %1; cvt.u32.u64 %0, t; }" : "=r"(a) : "l"(p));
    return a;
}

#define LDSM_X4(r, addr) \
    asm volatile("ldmatrix.sync.aligned.m8n8.x4.shared.b16 {%0,%1,%2,%3}, [%4];" \
        : "=r"((r)[0]), "=r"((r)[1]), "=r"((r)[2]), "=r"((r)[3]) : "r"(addr))

#define MMA16816(c, a, b0, b1) \
    asm volatile("mma.sync.aligned.m16n8k16.row.col.f32.bf16.bf16.f32 " \
        "{%0,%1,%2,%3}, {%4,%5,%6,%7}, {%8,%9}, {%0,%1,%2,%3};" \
        : "+f"((c)[0]), "+f"((c)[1]), "+f"((c)[2]), "+f"((c)[3]) \
        : "r"((a)[0]), "r"((a)[1]), "r"((a)[2]), "r"((a)[3]), "r"(b0), "r"(b1))

#define CPASYNC16(dst, src) \
    asm volatile("cp.async.cg.shared.global [%0], [%1], 16;" :: "r"(dst), "l"(src))

static __device__ __forceinline__ void cvt8u(const float* v, uint32_t* hi, uint32_t* lo) {
#pragma unroll
    for (int j = 0; j < 4; j++) {
        __nv_bfloat162 h = __float22bfloat162_rn(make_float2(v[2*j], v[2*j+1]));
        float g0 = __bfloat162float(h.x), g1 = __bfloat162float(h.y);
        __nv_bfloat162 l = __float22bfloat162_rn(make_float2(v[2*j]-g0, v[2*j+1]-g1));
        hi[j] = *(uint32_t*)&h; lo[j] = *(uint32_t*)&l;
    }
}

// ---------------- pack: fp32 -> bf16 hi/lo 128x16 chunks ----------------
__global__ void pack_tiles(const float* __restrict__ src, uint8_t* __restrict__ dst,
                           int K, int nslab, int Nreal, int nChunks)
{
    for (int id = blockIdx.x * blockDim.x + threadIdx.x; id < nChunks;
         id += gridDim.x * blockDim.x) {
        const int tile = id >> 8, w = id & 255;
        const int r = w >> 1, g = (w & 1) << 3;
        const int mt = tile / nslab, s = tile - mt * nslab;
        const int row = mt * 128 + r;
        float v[8] = {0.f,0.f,0.f,0.f,0.f,0.f,0.f,0.f};
        if (row < Nreal) {
            const float* p = src + (size_t)row * K + s * 16 + g;
            *(float4*)&v[0] = *(const float4*)p;
            *(float4*)&v[4] = *(const float4*)(p + 4);
        }
        uint32_t hi[4], lo[4];
        cvt8u(v, hi, lo);
        uint8_t* base = dst + (size_t)tile * 12288 + r * 48 + g * 2;
        *(uint4*)base          = *(uint4*)hi;
        *(uint4*)(base + 6144) = *(uint4*)lo;
    }
}

// ---------------- fused silu(gate)*up -> packed A chunks for down GEMM ----------------
__global__ void pack_silu(const float* __restrict__ guf, uint8_t* __restrict__ dst,
                          int nChunks)
{
    for (int id = blockIdx.x * blockDim.x + threadIdx.x; id < nChunks;
         id += gridDim.x * blockDim.x) {
        const int tile = id >> 8, w = id & 255;
        const int r = w >> 1, g = (w & 1) << 3;
        const int mt = tile / 344, s = tile - mt * 344;
        const int row = mt * 128 + r;
        const float* p = guf + (size_t)row * 11008 + s * 16 + g;
        float vg[8], vu[8], v[8];
        *(float4*)&vg[0] = *(const float4*)p;
        *(float4*)&vg[4] = *(const float4*)(p + 4);
        *(float4*)&vu[0] = *(const float4*)(p + INTERSZ);
        *(float4*)&vu[4] = *(const float4*)(p + INTERSZ + 4);
#pragma unroll
        for (int j = 0; j < 8; j++)
            v[j] = vu[j] * vg[j] / (1.f + expf(-vg[j]));
        uint32_t hi[4], lo[4];
        cvt8u(v, hi, lo);
        uint8_t* base = dst + (size_t)tile * 12288 + r * 48 + g * 2;
        *(uint4*)base          = *(uint4*)hi;
        *(uint4*)(base + 6144) = *(uint4*)lo;
    }
}

// ================= bf16x3 GEMM, 4-stage x K16 cp.async pipeline =================
// stage: Ahi(6144) Alo(6144) Bhi(6144) Blo(6144) = 24576 B; 4 stages = 96 KB.
#define STG 24576
#define GSMEM (4*STG)

__global__ __launch_bounds__(256, 2) void gemm_mma(
    const uint8_t* __restrict__ Ap, const uint8_t* __restrict__ Bp,
    float* __restrict__ C, const float* __restrict__ addv,
    int N, int nslab, int addflag)
{
    extern __shared__ char sm[];
    const int tid  = threadIdx.x;
    const int warp = tid >> 5, lane = tid & 31;
    const int wm = warp >> 2, wn = warp & 3;       // 2 x 4 warps, warp tile 64x32
    const uint32_t sbase = smem_u32(sm);

    const uint8_t* aT = Ap + (size_t)blockIdx.x * nslab * 12288;
    const uint8_t* bT = Bp + (size_t)blockIdx.y * nslab * 12288;

    float acc[4][4][4];
#pragma unroll
    for (int i = 0; i < 4; i++)
#pragma unroll
        for (int j = 0; j < 4; j++)
#pragma unroll
            for (int r = 0; r < 4; r++) acc[i][j][r] = 0.f;

    // prologue: stages 0..2
#pragma unroll
    for (int ss = 0; ss < 3; ss++) {
        const uint32_t d = sbase + (uint32_t)ss * STG;
        const size_t o = (size_t)ss * 12288;
#pragma unroll
        for (int j = 0; j < 3; j++) {
            const uint32_t c = (uint32_t)tid * 16 + (uint32_t)j * 4096;
            CPASYNC16(d + c,         aT + o + c);
            CPASYNC16(d + 12288 + c, bT + o + c);
        }
        asm volatile("cp.async.commit_group;" ::: "memory");
    }

    const int lrow  = lane & 15;
    const int lcolb = (lane >> 4) << 3;

    for (int s = 0; s < nslab; s++) {
        asm volatile("cp.async.wait_group 2;" ::: "memory");
        __syncthreads();
        if (s + 3 < nslab) {
            const uint32_t d = sbase + (uint32_t)((s + 3) & 3) * STG;
            const size_t o = (size_t)(s + 3) * 12288;
#pragma unroll
            for (int j = 0; j < 3; j++) {
                const uint32_t c = (uint32_t)tid * 16 + (uint32_t)j * 4096;
                CPASYNC16(d + c,         aT + o + c);
                CPASYNC16(d + 12288 + c, bT + o + c);
            }
        }
        asm volatile("cp.async.commit_group;" ::: "memory");   // keeps group numbering

        const uint32_t stb = sbase + (uint32_t)(s & 3) * STG;
        uint32_t bh[2][4], bl[2][4];
#pragma unroll
        for (int bt = 0; bt < 2; bt++) {
            const uint32_t off = (uint32_t)(((wn*32 + bt*16 + lrow) * 24 + lcolb) * 2);
            LDSM_X4(bh[bt], stb + 12288 + off);
            LDSM_X4(bl[bt], stb + 18432 + off);
        }
#pragma unroll
        for (int mt = 0; mt < 4; mt++) {
            uint32_t ah[4], al[4];
            const uint32_t off = (uint32_t)(((wm*64 + mt*16 + lrow) * 24 + lcolb) * 2);
            LDSM_X4(ah, stb + off);
            LDSM_X4(al, stb + 6144 + off);
#pragma unroll
            for (int nt = 0; nt < 4; nt++) {
                const int bt = nt >> 1, sel = nt & 1;
                const uint32_t b0h = bh[bt][sel], b1h = bh[bt][2+sel];
                const uint32_t b0l = bl[bt][sel], b1l = bl[bt][2+sel];
                MMA16816(acc[mt][nt], ah, b0h, b1h);
                MMA16816(acc[mt][nt], al, b0h, b1h);
                MMA16816(acc[mt][nt], ah, b0l, b1l);
            }
        }
    }

    // ---- epilogue ----
    const int g  = lane >> 2;
    const int t4 = lane & 3;
    const int bm = blockIdx.x * 128, bn = blockIdx.y * 128;
    __syncthreads();
#pragma unroll
    for (int mt = 0; mt < 4; mt++) {
        const int row = bm + wm*64 + mt*16 + g;
#pragma unroll
        for (int nt = 0; nt < 4; nt++) {
            const int col = bn + wn*32 + nt*8 + t4*2;
            if (col < N) {
                float2 v0 = make_float2(acc[mt][nt][0], acc[mt][nt][1]);
                float2 v1 = make_float2(acc[mt][nt][2], acc[mt][nt][3]);
                const size_t i0 = (size_t)row * N + col;
                const size_t i1 = (size_t)(row + 8) * N + col;
                if (addflag) {
                    const float2 a0 = *(const float2*)(addv + i0);
                    const float2 a1 = *(const float2*)(addv + i1);
                    v0.x += a0.x; v0.y += a0.y; v1.x += a1.x; v1.y += a1.y;
                }
                *(float2*)(C + i0) = v0;
                *(float2*)(C + i1) = v1;
            }
        }
    }
}

// ---------------- RMSNorm (optionally * mask) ----------------
__global__ void rmsnorm_kernel(const float* __restrict__ x,
                               const float* __restrict__ w,
                               const float* __restrict__ mask,
                               float* __restrict__ out)
{
    const int m = blockIdx.x;
    const float* row = x + (size_t)m * DMODEL;
    float s = 0.f;
    for (int i = threadIdx.x; i < DMODEL; i += 256) { float v = row[i]; s += v * v; }
#pragma unroll
    for (int o = 16; o > 0; o >>= 1) s += __shfl_xor_sync(0xffffffffu, s, o);
    __shared__ float red[8];
    const int lane = threadIdx.x & 31, wid = threadIdx.x >> 5;
    if (lane == 0) red[wid] = s;
    __syncthreads();
    if (wid == 0) {
        s = (lane < 8) ? red[lane] : 0.f;
#pragma unroll
        for (int o = 4; o > 0; o >>= 1) s += __shfl_xor_sync(0xffffffffu, s, o);
        if (lane == 0) red[0] = s;
    }
    __syncthreads();
    const float inv = rsqrtf(red[0] * (1.0f / (float)DMODEL) + 1e-6f);
    const float mk = mask ? mask[m] : 1.f;
    for (int i = threadIdx.x; i < DMODEL; i += 256)
        out[(size_t)m * DMODEL + i] = row[i] * inv * w[i] * mk;
}

// ---------------- causal depthwise conv1d ----------------
__global__ void conv_kernel(const float* __restrict__ zx,
                            const float* __restrict__ cw,
                            const float* __restrict__ cb,
                            float* __restrict__ xbc)
{
    const int m = blockIdx.x;
    const int t = m & (SEQ - 1);
    for (int c = threadIdx.x; c < CONVDIM; c += 256) {
        float acc = cb[c];
#pragma unroll
        for (int j = 0; j < DCONV; j++) {
            const int tt = t - (DCONV - 1) + j;
            if (tt >= 0)
                acc += cw[c * DCONV + j] *
                       zx[(size_t)(m - (DCONV - 1) + j) * DPROJ + DINNER + c];
        }
        xbc[(size_t)m * CONVDIM + c] = acc;
    }
}

// ---------------- sequential SSM scan + gating (vectorized smem) ----------------
// per-buffer layout (floats): x[8][64] | B[8][64] | C[8][64] | z[8][64] | a[8] pad->2064
#define CHK 8
#define SBUF 2064
__global__ __launch_bounds__(256) void scan_kernel(
    const float* __restrict__ xbc, const float* __restrict__ zx,
    const float* __restrict__ Dv, const float* __restrict__ zb,
    float* __restrict__ gated)
{
    const int bh = blockIdx.x;
    const int b = bh >> 5;
    const int h = bh & 31;
    const int tid = threadIdx.x;
    const int p = tid >> 2;
    const int q = tid & 3;
    const int n0 = q << 4;

    __shared__ __align__(16) float sd[2][SBUF];

    int lts[9], loff[9], lkind[9], lsh[9];
    bool lvalid[9];
#pragma unroll
    for (int k = 0; k < 9; k++) {
        const int e = tid + k * 256;
        lvalid[k] = (e < CHK * 257);
        const int tsub = e / 257;
        const int j = e - tsub * 257;
        lts[k] = tsub;
        if (j < 64)        { lkind[k] = 0; loff[k] = h * HEADDIM + j;                     lsh[k] = tsub*64 + j; }
        else if (j < 128)  { lkind[k] = 0; loff[k] = DINNER + h * DSTATE + (j - 64);      lsh[k] = 512 + tsub*64 + (j-64); }
        else if (j < 192)  { lkind[k] = 0; loff[k] = DINNER + NHEADS*DSTATE + h*DSTATE + (j-128); lsh[k] = 1024 + tsub*64 + (j-128); }
        else if (j < 256)  { lkind[k] = 1; loff[k] = h * HEADDIM + (j - 192);             lsh[k] = 1536 + tsub*64 + (j-192); }
        else               { lkind[k] = 2; loff[k] = 2*DINNER + 2*NHEADS*DSTATE + h;      lsh[k] = 2048 + tsub; }
    }
#pragma unroll
    for (int k = 0; k < 9; k++) {
        if (lvalid[k]) {
            const size_t m = (size_t)b * SEQ + lts[k];
            float v;
            if (lkind[k] == 0) v = xbc[m * CONVDIM + loff[k]];
            else               v = zx[m * DPROJ + loff[k]];
            if (lkind[k] == 2) v = 1.f / (1.f + expf(v));
            sd[0][lsh[k]] = v;
        }
    }
    __syncthreads();

    float st[16];
#pragma unroll
    for (int i = 0; i < 16; i++) st[i] = 0.f;
    const float Dh = Dv[h];
    const float zbias = zb[h * HEADDIM + p];

    const int NC = SEQ / CHK;
    for (int c = 0; c < NC; c++) {
        const int cur = c & 1;
        const bool pre = (c + 1 < NC);
        float regv[9];
        if (pre) {
#pragma unroll
            for (int k = 0; k < 9; k++) {
                if (lvalid[k]) {
                    const size_t m = (size_t)b * SEQ + (c + 1) * CHK + lts[k];
                    float v;
                    if (lkind[k] == 0) v = xbc[m * CONVDIM + loff[k]];
                    else               v = zx[m * DPROJ + loff[k]];
                    if (lkind[k] == 2) v = 1.f / (1.f + expf(v));
                    regv[k] = v;
                }
            }
        }
        const float* sb = sd[cur];
#pragma unroll
        for (int tsub = 0; tsub < CHK; tsub++) {
            const float a  = sb[2048 + tsub];
            const float xv = sb[tsub*64 + p];
            const float4* Bp4 = (const float4*)(sb + 512 + tsub*64 + n0);
            const float4* Cp4 = (const float4*)(sb + 1024 + tsub*64 + n0);
            float Bv[16], Cv[16];
            *(float4*)&Bv[0]  = Bp4[0]; *(float4*)&Bv[4]  = Bp4[1];
            *(float4*)&Bv[8]  = Bp4[2]; *(float4*)&Bv[12] = Bp4[3];
            *(float4*)&Cv[0]  = Cp4[0]; *(float4*)&Cv[4]  = Cp4[1];
            *(float4*)&Cv[8]  = Cp4[2]; *(float4*)&Cv[12] = Cp4[3];
            float y = 0.f;
#pragma unroll
            for (int i = 0; i < 16; i++) {
                st[i] = a * st[i] + xv * Bv[i];
                y = fmaf(st[i], Cv[i], y);
            }
            y += __shfl_xor_sync(0xffffffffu, y, 1);
            y += __shfl_xor_sync(0xffffffffu, y, 2);
            if (q == 0) {
                const size_t m = (size_t)b * SEQ + c * CHK + tsub;
                const float zval = sb[1536 + tsub*64 + p] + zbias;
                const float sig = 1.f / (1.f + expf(-zval));
                gated[m * DMODEL + h * HEADDIM + p] = (y + Dh * xv) * (zval * sig);
            }
        }
        if (pre) {
#pragma unroll
            for (int k = 0; k < 9; k++)
                if (lvalid[k]) sd[cur ^ 1][lsh[k]] = regv[k];
        }
        __syncthreads();
    }
}

// ---------------- launcher ----------------
extern "C" void kernel_launch(void* const* d_in, const int* in_sizes, int n_in,
                              void* d_out, int out_size)
{
    (void)in_sizes; (void)n_in; (void)out_size;
    const float* hidden     = (const float*)d_in[0];
    const float* mask       = (const float*)d_in[1];
    const float* in_proj_w  = (const float*)d_in[2];
    const float* conv_w     = (const float*)d_in[3];
    const float* conv_b     = (const float*)d_in[4];
    const float* z_bias     = (const float*)d_in[5];
    const float* Dv         = (const float*)d_in[6];
    const float* out_proj_w = (const float*)d_in[7];
    const float* ln1_w      = (const float*)d_in[8];
    const float* ln2_w      = (const float*)d_in[9];
    const float* gate_w     = (const float*)d_in[10];
    const float* up_w       = (const float*)d_in[11];
    const float* down_w     = (const float*)d_in[12];
    float* out = (float*)d_out;

    float *xnorm, *zx, *xbc, *gated, *res2, *guf;
    uint8_t *pa, *pb;
    cudaGetSymbolAddress((void**)&xnorm, g_xnorm);
    cudaGetSymbolAddress((void**)&zx,    g_zx);
    cudaGetSymbolAddress((void**)&xbc,   g_xbc);
    cudaGetSymbolAddress((void**)&gated, g_gated);
    cudaGetSymbolAddress((void**)&res2,  g_res2);
    cudaGetSymbolAddress((void**)&guf,   g_guf);
    cudaGetSymbolAddress((void**)&pa,    g_pa);
    cudaGetSymbolAddress((void**)&pb,    g_pb);

    cudaFuncSetAttribute(gemm_mma, cudaFuncAttributeMaxDynamicSharedMemorySize, GSMEM);
    const int PKG = 2048;

    // ---- mixer ----
    rmsnorm_kernel<<<MROWS, 256>>>(hidden, ln1_w, mask, xnorm);
    pack_tiles<<<PKG, 256>>>(xnorm, pa, 2048, 128, MROWS, 32*128*256);
    pack_tiles<<<PKG, 256>>>(in_proj_w, pb, 2048, 128, DPROJ, 65*128*256);
    gemm_mma<<<dim3(32, 65), 256, GSMEM>>>(pa, pb, zx, nullptr, DPROJ, 128, 0);

    conv_kernel<<<MROWS, 256>>>(zx, conv_w, conv_b, xbc);
    scan_kernel<<<BATCH * NHEADS, 256>>>(xbc, zx, Dv, z_bias, gated);

    pack_tiles<<<PKG, 256>>>(gated, pa, 2048, 128, MROWS, 32*128*256);
    pack_tiles<<<PKG, 256>>>(out_proj_w, pb, 2048, 128, DMODEL, 16*128*256);
    gemm_mma<<<dim3(32, 16), 256, GSMEM>>>(pa, pb, res2, hidden, DMODEL, 128, 1);

    // ---- MLP ----
    rmsnorm_kernel<<<MROWS, 256>>>(res2, ln2_w, nullptr, xnorm);
    pack_tiles<<<PKG, 256>>>(xnorm, pa, 2048, 128, MROWS, 32*128*256);
    pack_tiles<<<PKG, 256>>>(gate_w, pb, 2048, 128, INTERSZ, 43*128*256);
    pack_tiles<<<PKG, 256>>>(up_w, pb + (size_t)43*128*12288, 2048, 128, INTERSZ, 43*128*256);
    gemm_mma<<<dim3(32, 86), 256, GSMEM>>>(pa, pb, guf, nullptr, 11008, 128, 0);

    pack_silu<<<PKG, 256>>>(guf, pa, 32*344*256);
    pack_tiles<<<PKG, 256>>>(down_w, pb, 5504, 344, DMODEL, 16*344*256);
    gemm_mma<<<dim3(32, 16), 256, GSMEM>>>(pa, pb, out, res2, DMODEL, 344, 1);
}

// round 8
// speedup vs baseline: 1.0252x; 1.0252x over previous
#include <cuda_runtime.h>
#include <cuda_bf16.h>
#include <math.h>
#include <stdint.h>

#define BATCH   2
#define SEQ     2048
#define DMODEL  2048
#define NHEADS  32
#define DSTATE  64
#define HEADDIM 64
#define DCONV   4
#define INTERSZ 5504
#define DINNER  DMODEL
#define CONVDIM (DINNER + 2*NHEADS*DSTATE)              /* 6144 */
#define DPROJ   (2*DINNER + 2*NHEADS*DSTATE + NHEADS)   /* 8224 */
#define MROWS   (BATCH*SEQ)                             /* 4096 */

// ---------------- scratch ----------------
__device__ float g_xnorm[(size_t)MROWS * DMODEL];
__device__ float g_zx   [(size_t)MROWS * DPROJ];
__device__ float g_xbc  [(size_t)MROWS * CONVDIM];
__device__ float g_gated[(size_t)MROWS * DMODEL];
__device__ float g_res2 [(size_t)MROWS * DMODEL];
__device__ float g_guf  [(size_t)MROWS * 11008];
// packed bf16 hi/lo tiles: tile = 128 rows x 32 cols, 80B rows,
// hi plane 10240B then lo plane 10240B => 20480B per (tile,slab32).
__device__ __align__(128) uint8_t g_pa[(size_t)32 * 172 * 20480];  /* 113 MB */
__device__ __align__(128) uint8_t g_pb[(size_t)86 * 64  * 20480];  /* 113 MB */

static __device__ __forceinline__ uint32_t smem_u32(const void* p) {
    uint32_t a;
    asm("{ .reg .u64 t; cvta.to.shared.u64 t, %1; cvt.u32.u64 %0, t; }" : "=r"(a) : "l"(p));
    return a;
}

#define LDSM_X4(r, addr) \
    asm volatile("ldmatrix.sync.aligned.m8n8.x4.shared.b16 {%0,%1,%2,%3}, [%4];" \
        : "=r"((r)[0]), "=r"((r)[1]), "=r"((r)[2]), "=r"((r)[3]) : "r"(addr))

#define MMA16816(c, a, b0, b1) \
    asm volatile("mma.sync.aligned.m16n8k16.row.col.f32.bf16.bf16.f32 " \
        "{%0,%1,%2,%3}, {%4,%5,%6,%7}, {%8,%9}, {%0,%1,%2,%3};" \
        : "+f"((c)[0]), "+f"((c)[1]), "+f"((c)[2]), "+f"((c)[3]) \
        : "r"((a)[0]), "r"((a)[1]), "r"((a)[2]), "r"((a)[3]), "r"(b0), "r"(b1))

#define CPASYNC16(dst, src) \
    asm volatile("cp.async.cg.shared.global [%0], [%1], 16;" :: "r"(dst), "l"(src))

static __device__ __forceinline__ void cvt8u(const float* v, uint32_t* hi, uint32_t* lo) {
#pragma unroll
    for (int j = 0; j < 4; j++) {
        __nv_bfloat162 h = __float22bfloat162_rn(make_float2(v[2*j], v[2*j+1]));
        float g0 = __bfloat162float(h.x), g1 = __bfloat162float(h.y);
        __nv_bfloat162 l = __float22bfloat162_rn(make_float2(v[2*j]-g0, v[2*j+1]-g1));
        hi[j] = *(uint32_t*)&h; lo[j] = *(uint32_t*)&l;
    }
}

// ---------------- pack: fp32 -> bf16 hi/lo 128x32 tiles ----------------
__global__ void pack_tiles(const float* __restrict__ src, uint8_t* __restrict__ dst,
                           int K, int nslab, int Nreal, int nChunks)
{
    for (int id = blockIdx.x * blockDim.x + threadIdx.x; id < nChunks;
         id += gridDim.x * blockDim.x) {
        const int tile = id >> 9;
        const int w = id & 511;
        const int r = w >> 2, g = w & 3;
        const int mt = tile / nslab;
        const int s  = tile - mt * nslab;
        const int row = mt * 128 + r;
        float v[8] = {0.f,0.f,0.f,0.f,0.f,0.f,0.f,0.f};
        if (row < Nreal) {
            const float* p = src + (size_t)row * K + s * 32 + g * 8;
            *(float4*)&v[0] = *(const float4*)p;
            *(float4*)&v[4] = *(const float4*)(p + 4);
        }
        uint32_t hi[4], lo[4];
        cvt8u(v, hi, lo);
        uint8_t* base = dst + (size_t)tile * 20480 + r * 80 + g * 16;
        *(uint4*)base            = *(uint4*)hi;
        *(uint4*)(base + 10240)  = *(uint4*)lo;
    }
}

// ---------------- fused silu(gate)*up -> packed A tiles for down GEMM ----------------
__global__ void pack_silu(const float* __restrict__ guf, uint8_t* __restrict__ dst,
                          int nChunks)
{
    for (int id = blockIdx.x * blockDim.x + threadIdx.x; id < nChunks;
         id += gridDim.x * blockDim.x) {
        const int tile = id >> 9;
        const int w = id & 511;
        const int r = w >> 2, g = w & 3;
        const int mt = tile / 172;
        const int s  = tile - mt * 172;
        const int row = mt * 128 + r;
        const float* p = guf + (size_t)row * 11008 + s * 32 + g * 8;
        float vg[8], vu[8], v[8];
        *(float4*)&vg[0] = *(const float4*)p;
        *(float4*)&vg[4] = *(const float4*)(p + 4);
        *(float4*)&vu[0] = *(const float4*)(p + INTERSZ);
        *(float4*)&vu[4] = *(const float4*)(p + INTERSZ + 4);
#pragma unroll
        for (int j = 0; j < 8; j++)
            v[j] = vu[j] * vg[j] / (1.f + expf(-vg[j]));
        uint32_t hi[4], lo[4];
        cvt8u(v, hi, lo);
        uint8_t* base = dst + (size_t)tile * 20480 + r * 80 + g * 16;
        *(uint4*)base            = *(uint4*)hi;
        *(uint4*)(base + 10240)  = *(uint4*)lo;
    }
}

// ================= bf16x3 GEMM, packed operands, 2-stage K32 cp.async =================
// stage: Ahi(10240) Alo(10240) Bhi(10240) Blo(10240) = 40960 B; 2 stages.
#define OFF_AL 10240
#define OFF_BH 20480
#define OFF_BL 30720
#define STAGE  40960
#define GSMEM  (2*STAGE)

__global__ __launch_bounds__(256, 2) void gemm_mma(
    const uint8_t* __restrict__ Ap, const uint8_t* __restrict__ Bp,
    float* __restrict__ C, const float* __restrict__ addv,
    int N, int nslab, int addflag)
{
    extern __shared__ char sm[];
    const int tid  = threadIdx.x;
    const int warp = tid >> 5, lane = tid & 31;
    const int wm = warp >> 2, wn = warp & 3;       // 2 x 4 warps, warp tile 64x32
    const uint32_t sbase = smem_u32(sm);

    const uint8_t* aT = Ap + (size_t)blockIdx.x * nslab * 20480;
    const uint8_t* bT = Bp + (size_t)blockIdx.y * nslab * 20480;

    float acc[4][4][4];
#pragma unroll
    for (int i = 0; i < 4; i++)
#pragma unroll
        for (int j = 0; j < 4; j++)
#pragma unroll
            for (int r = 0; r < 4; r++) acc[i][j][r] = 0.f;

    // prologue: stage 0
    {
        const uint32_t d = sbase;
#pragma unroll
        for (int j = 0; j < 5; j++) {
            const uint32_t cid = (uint32_t)tid * 16 + (uint32_t)j * 4096;
            CPASYNC16(d + cid,         aT + cid);
            CPASYNC16(d + 20480 + cid, bT + cid);
        }
        asm volatile("cp.async.commit_group;" ::: "memory");
    }

    const int lrow  = lane & 15;
    const int lcolb = (lane >> 4) << 3;

    for (int s = 0; s < nslab; s++) {
        asm volatile("cp.async.wait_group 0;" ::: "memory");
        __syncthreads();
        if (s + 1 < nslab) {
            const uint32_t d = sbase + (uint32_t)((s + 1) & 1) * STAGE;
            const uint8_t* an = aT + (size_t)(s + 1) * 20480;
            const uint8_t* bn = bT + (size_t)(s + 1) * 20480;
#pragma unroll
            for (int j = 0; j < 5; j++) {
                const uint32_t cid = (uint32_t)tid * 16 + (uint32_t)j * 4096;
                CPASYNC16(d + cid,         an + cid);
                CPASYNC16(d + 20480 + cid, bn + cid);
            }
            asm volatile("cp.async.commit_group;" ::: "memory");
        }
        const uint32_t stb = sbase + (uint32_t)(s & 1) * STAGE;
#pragma unroll
        for (int ks = 0; ks < 2; ks++) {
            const int k0 = ks * 16;
            uint32_t bh[2][4], bl[2][4];
#pragma unroll
            for (int bt = 0; bt < 2; bt++) {
                const uint32_t off = (uint32_t)(((wn*32 + bt*16 + lrow) * 40 + k0 + lcolb) * 2);
                LDSM_X4(bh[bt], stb + OFF_BH + off);
                LDSM_X4(bl[bt], stb + OFF_BL + off);
            }
#pragma unroll
            for (int mt = 0; mt < 4; mt++) {
                uint32_t ah[4], al[4];
                const uint32_t off = (uint32_t)(((wm*64 + mt*16 + lrow) * 40 + k0 + lcolb) * 2);
                LDSM_X4(ah, stb + off);
                LDSM_X4(al, stb + OFF_AL + off);
#pragma unroll
                for (int nt = 0; nt < 4; nt++) {
                    const int bt = nt >> 1, sel = nt & 1;
                    const uint32_t b0h = bh[bt][sel], b1h = bh[bt][2+sel];
                    const uint32_t b0l = bl[bt][sel], b1l = bl[bt][2+sel];
                    MMA16816(acc[mt][nt], ah, b0h, b1h);
                    MMA16816(acc[mt][nt], al, b0h, b1h);
                    MMA16816(acc[mt][nt], ah, b0l, b1l);
                }
            }
        }
        __syncthreads();
    }

    // ---- epilogue ----
    const int g  = lane >> 2;
    const int t4 = lane & 3;
    const int bm = blockIdx.x * 128, bn = blockIdx.y * 128;
#pragma unroll
    for (int mt = 0; mt < 4; mt++) {
        const int row = bm + wm*64 + mt*16 + g;
#pragma unroll
        for (int nt = 0; nt < 4; nt++) {
            const int col = bn + wn*32 + nt*8 + t4*2;
            if (col < N) {
                float2 v0 = make_float2(acc[mt][nt][0], acc[mt][nt][1]);
                float2 v1 = make_float2(acc[mt][nt][2], acc[mt][nt][3]);
                const size_t i0 = (size_t)row * N + col;
                const size_t i1 = (size_t)(row + 8) * N + col;
                if (addflag) {
                    const float2 a0 = *(const float2*)(addv + i0);
                    const float2 a1 = *(const float2*)(addv + i1);
                    v0.x += a0.x; v0.y += a0.y; v1.x += a1.x; v1.y += a1.y;
                }
                *(float2*)(C + i0) = v0;
                *(float2*)(C + i1) = v1;
            }
        }
    }
}

// ---------------- RMSNorm (optionally * mask) ----------------
__global__ void rmsnorm_kernel(const float* __restrict__ x,
                               const float* __restrict__ w,
                               const float* __restrict__ mask,
                               float* __restrict__ out)
{
    const int m = blockIdx.x;
    const float* row = x + (size_t)m * DMODEL;
    float s = 0.f;
    for (int i = threadIdx.x; i < DMODEL; i += 256) { float v = row[i]; s += v * v; }
#pragma unroll
    for (int o = 16; o > 0; o >>= 1) s += __shfl_xor_sync(0xffffffffu, s, o);
    __shared__ float red[8];
    const int lane = threadIdx.x & 31, wid = threadIdx.x >> 5;
    if (lane == 0) red[wid] = s;
    __syncthreads();
    if (wid == 0) {
        s = (lane < 8) ? red[lane] : 0.f;
#pragma unroll
        for (int o = 4; o > 0; o >>= 1) s += __shfl_xor_sync(0xffffffffu, s, o);
        if (lane == 0) red[0] = s;
    }
    __syncthreads();
    const float inv = rsqrtf(red[0] * (1.0f / (float)DMODEL) + 1e-6f);
    const float mk = mask ? mask[m] : 1.f;
    for (int i = threadIdx.x; i < DMODEL; i += 256)
        out[(size_t)m * DMODEL + i] = row[i] * inv * w[i] * mk;
}

// ---------------- causal depthwise conv1d ----------------
__global__ void conv_kernel(const float* __restrict__ zx,
                            const float* __restrict__ cw,
                            const float* __restrict__ cb,
                            float* __restrict__ xbc)
{
    const int m = blockIdx.x;
    const int t = m & (SEQ - 1);
    for (int c = threadIdx.x; c < CONVDIM; c += 256) {
        float acc = cb[c];
#pragma unroll
        for (int j = 0; j < DCONV; j++) {
            const int tt = t - (DCONV - 1) + j;
            if (tt >= 0)
                acc += cw[c * DCONV + j] *
                       zx[(size_t)(m - (DCONV - 1) + j) * DPROJ + DINNER + c];
        }
        xbc[(size_t)m * CONVDIM + c] = acc;
    }
}

// ---------------- sequential SSM scan + gating (vectorized smem) ----------------
// per-buffer layout (floats): x[8][64] | B[8][64] | C[8][64] | z[8][64] | a[8] pad->2064
#define CHK 8
#define SBUF 2064
__global__ __launch_bounds__(256) void scan_kernel(
    const float* __restrict__ xbc, const float* __restrict__ zx,
    const float* __restrict__ Dv, const float* __restrict__ zb,
    float* __restrict__ gated)
{
    const int bh = blockIdx.x;
    const int b = bh >> 5;
    const int h = bh & 31;
    const int tid = threadIdx.x;
    const int p = tid >> 2;
    const int q = tid & 3;
    const int n0 = q << 4;

    __shared__ __align__(16) float sd[2][SBUF];

    int lts[9], loff[9], lkind[9], lsh[9];
    bool lvalid[9];
#pragma unroll
    for (int k = 0; k < 9; k++) {
        const int e = tid + k * 256;
        lvalid[k] = (e < CHK * 257);
        const int tsub = e / 257;
        const int j = e - tsub * 257;
        lts[k] = tsub;
        if (j < 64)        { lkind[k] = 0; loff[k] = h * HEADDIM + j;                     lsh[k] = tsub*64 + j; }
        else if (j < 128)  { lkind[k] = 0; loff[k] = DINNER + h * DSTATE + (j - 64);      lsh[k] = 512 + tsub*64 + (j-64); }
        else if (j < 192)  { lkind[k] = 0; loff[k] = DINNER + NHEADS*DSTATE + h*DSTATE + (j-128); lsh[k] = 1024 + tsub*64 + (j-128); }
        else if (j < 256)  { lkind[k] = 1; loff[k] = h * HEADDIM + (j - 192);             lsh[k] = 1536 + tsub*64 + (j-192); }
        else               { lkind[k] = 2; loff[k] = 2*DINNER + 2*NHEADS*DSTATE + h;      lsh[k] = 2048 + tsub; }
    }
#pragma unroll
    for (int k = 0; k < 9; k++) {
        if (lvalid[k]) {
            const size_t m = (size_t)b * SEQ + lts[k];
            float v;
            if (lkind[k] == 0) v = xbc[m * CONVDIM + loff[k]];
            else               v = zx[m * DPROJ + loff[k]];
            if (lkind[k] == 2) v = 1.f / (1.f + expf(v));
            sd[0][lsh[k]] = v;
        }
    }
    __syncthreads();

    float st[16];
#pragma unroll
    for (int i = 0; i < 16; i++) st[i] = 0.f;
    const float Dh = Dv[h];
    const float zbias = zb[h * HEADDIM + p];

    const int NC = SEQ / CHK;
    for (int c = 0; c < NC; c++) {
        const int cur = c & 1;
        const bool pre = (c + 1 < NC);
        float regv[9];
        if (pre) {
#pragma unroll
            for (int k = 0; k < 9; k++) {
                if (lvalid[k]) {
                    const size_t m = (size_t)b * SEQ + (c + 1) * CHK + lts[k];
                    float v;
                    if (lkind[k] == 0) v = xbc[m * CONVDIM + loff[k]];
                    else               v = zx[m * DPROJ + loff[k]];
                    if (lkind[k] == 2) v = 1.f / (1.f + expf(v));
                    regv[k] = v;
                }
            }
        }
        const float* sb = sd[cur];
#pragma unroll
        for (int tsub = 0; tsub < CHK; tsub++) {
            const float a  = sb[2048 + tsub];
            const float xv = sb[tsub*64 + p];
            const float4* Bp4 = (const float4*)(sb + 512 + tsub*64 + n0);
            const float4* Cp4 = (const float4*)(sb + 1024 + tsub*64 + n0);
            float Bv[16], Cv[16];
            *(float4*)&Bv[0]  = Bp4[0]; *(float4*)&Bv[4]  = Bp4[1];
            *(float4*)&Bv[8]  = Bp4[2]; *(float4*)&Bv[12] = Bp4[3];
            *(float4*)&Cv[0]  = Cp4[0]; *(float4*)&Cv[4]  = Cp4[1];
            *(float4*)&Cv[8]  = Cp4[2]; *(float4*)&Cv[12] = Cp4[3];
            float y = 0.f;
#pragma unroll
            for (int i = 0; i < 16; i++) {
                st[i] = a * st[i] + xv * Bv[i];
                y = fmaf(st[i], Cv[i], y);
            }
            y += __shfl_xor_sync(0xffffffffu, y, 1);
            y += __shfl_xor_sync(0xffffffffu, y, 2);
            if (q == 0) {
                const size_t m = (size_t)b * SEQ + c * CHK + tsub;
                const float zval = sb[1536 + tsub*64 + p] + zbias;
                const float sig = 1.f / (1.f + expf(-zval));
                gated[m * DMODEL + h * HEADDIM + p] = (y + Dh * xv) * (zval * sig);
            }
        }
        if (pre) {
#pragma unroll
            for (int k = 0; k < 9; k++)
                if (lvalid[k]) sd[cur ^ 1][lsh[k]] = regv[k];
        }
        __syncthreads();
    }
}

// ---------------- launcher ----------------
extern "C" void kernel_launch(void* const* d_in, const int* in_sizes, int n_in,
                              void* d_out, int out_size)
{
    (void)in_sizes; (void)n_in; (void)out_size;
    const float* hidden     = (const float*)d_in[0];
    const float* mask       = (const float*)d_in[1];
    const float* in_proj_w  = (const float*)d_in[2];
    const float* conv_w     = (const float*)d_in[3];
    const float* conv_b     = (const float*)d_in[4];
    const float* z_bias     = (const float*)d_in[5];
    const float* Dv         = (const float*)d_in[6];
    const float* out_proj_w = (const float*)d_in[7];
    const float* ln1_w      = (const float*)d_in[8];
    const float* ln2_w      = (const float*)d_in[9];
    const float* gate_w     = (const float*)d_in[10];
    const float* up_w       = (const float*)d_in[11];
    const float* down_w     = (const float*)d_in[12];
    float* out = (float*)d_out;

    float *xnorm, *zx, *xbc, *gated, *res2, *guf;
    uint8_t *pa, *pb;
    cudaGetSymbolAddress((void**)&xnorm, g_xnorm);
    cudaGetSymbolAddress((void**)&zx,    g_zx);
    cudaGetSymbolAddress((void**)&xbc,   g_xbc);
    cudaGetSymbolAddress((void**)&gated, g_gated);
    cudaGetSymbolAddress((void**)&res2,  g_res2);
    cudaGetSymbolAddress((void**)&guf,   g_guf);
    cudaGetSymbolAddress((void**)&pa,    g_pa);
    cudaGetSymbolAddress((void**)&pb,    g_pb);

    cudaFuncSetAttribute(gemm_mma, cudaFuncAttributeMaxDynamicSharedMemorySize, GSMEM);
    const int PKG = 4096;

    // ---- mixer ----
    rmsnorm_kernel<<<MROWS, 256>>>(hidden, ln1_w, mask, xnorm);
    pack_tiles<<<PKG, 256>>>(xnorm, pa, 2048, 64, MROWS, 32*64*512);
    pack_tiles<<<PKG, 256>>>(in_proj_w, pb, 2048, 64, DPROJ, 65*64*512);
    gemm_mma<<<dim3(32, 65), 256, GSMEM>>>(pa, pb, zx, nullptr, DPROJ, 64, 0);

    conv_kernel<<<MROWS, 256>>>(zx, conv_w, conv_b, xbc);
    scan_kernel<<<BATCH * NHEADS, 256>>>(xbc, zx, Dv, z_bias, gated);

    pack_tiles<<<PKG, 256>>>(gated, pa, 2048, 64, MROWS, 32*64*512);
    pack_tiles<<<PKG, 256>>>(out_proj_w, pb, 2048, 64, DMODEL, 16*64*512);
    gemm_mma<<<dim3(32, 16), 256, GSMEM>>>(pa, pb, res2, hidden, DMODEL, 64, 1);

    // ---- MLP ----
    rmsnorm_kernel<<<MROWS, 256>>>(res2, ln2_w, nullptr, xnorm);
    pack_tiles<<<PKG, 256>>>(xnorm, pa, 2048, 64, MROWS, 32*64*512);
    pack_tiles<<<PKG, 256>>>(gate_w, pb, 2048, 64, INTERSZ, 43*64*512);
    pack_tiles<<<PKG, 256>>>(up_w, pb + (size_t)43*64*20480, 2048, 64, INTERSZ, 43*64*512);
    gemm_mma<<<dim3(32, 86), 256, GSMEM>>>(pa, pb, guf, nullptr, 11008, 64, 0);

    pack_silu<<<PKG, 256>>>(guf, pa, 32*172*512);
    pack_tiles<<<PKG, 256>>>(down_w, pb, 5504, 172, DMODEL, 16*172*512);
    gemm_mma<<<dim3(32, 16), 256, GSMEM>>>(pa, pb, out, res2, DMODEL, 172, 1);
}

// round 9
// speedup vs baseline: 1.0525x; 1.0267x over previous
#include <cuda_runtime.h>
#include <cuda_bf16.h>
#include <math.h>
#include <stdint.h>

#define BATCH   2
#define SEQ     2048
#define DMODEL  2048
#define NHEADS  32
#define DSTATE  64
#define HEADDIM 64
#define DCONV   4
#define INTERSZ 5504
#define DINNER  DMODEL
#define CONVDIM (DINNER + 2*NHEADS*DSTATE)              /* 6144 */
#define DPROJ   (2*DINNER + 2*NHEADS*DSTATE + NHEADS)   /* 8224 */
#define MROWS   (BATCH*SEQ)                             /* 4096 */

// ---------------- scratch ----------------
__device__ float g_xnorm[(size_t)MROWS * DMODEL];
__device__ float g_zx   [(size_t)MROWS * DPROJ];
__device__ float g_xbc  [(size_t)MROWS * CONVDIM];
__device__ float g_gated[(size_t)MROWS * DMODEL];
__device__ float g_res2 [(size_t)MROWS * DMODEL];
__device__ float g_guf  [(size_t)MROWS * 11008];
// packed bf16 hi/lo tile images: tile = 128 rows x 32 cols, 64B rows with XOR
// swizzle (c' = c ^ ((r>>1)&3), c in 16B units). hi plane 8192B + lo plane
// 8192B = 16384B per (tile,slab32).
__device__ __align__(128) uint8_t g_pa[(size_t)32 * 172 * 16384];  /* 90 MB */
__device__ __align__(128) uint8_t g_pb[(size_t)86 * 64  * 16384];  /* 90 MB */

static __device__ __forceinline__ uint32_t smem_u32(const void* p) {
    uint32_t a;
    asm("{ .reg .u64 t; cvta.to.shared.u64 t, %1; cvt.u32.u64 %0, t; }" : "=r"(a) : "l"(p));
    return a;
}

#define LDSM_X4(r, addr) \
    asm volatile("ldmatrix.sync.aligned.m8n8.x4.shared.b16 {%0,%1,%2,%3}, [%4];" \
        : "=r"((r)[0]), "=r"((r)[1]), "=r"((r)[2]), "=r"((r)[3]) : "r"(addr))

#define MMA16816(c, a, b0, b1) \
    asm volatile("mma.sync.aligned.m16n8k16.row.col.f32.bf16.bf16.f32 " \
        "{%0,%1,%2,%3}, {%4,%5,%6,%7}, {%8,%9}, {%0,%1,%2,%3};" \
        : "+f"((c)[0]), "+f"((c)[1]), "+f"((c)[2]), "+f"((c)[3]) \
        : "r"((a)[0]), "r"((a)[1]), "r"((a)[2]), "r"((a)[3]), "r"(b0), "r"(b1))

#define CPASYNC16(dst, src) \
    asm volatile("cp.async.cg.shared.global [%0], [%1], 16;" :: "r"(dst), "l"(src))

static __device__ __forceinline__ void cvt8u(const float* v, uint32_t* hi, uint32_t* lo) {
#pragma unroll
    for (int j = 0; j < 4; j++) {
        __nv_bfloat162 h = __float22bfloat162_rn(make_float2(v[2*j], v[2*j+1]));
        float g0 = __bfloat162float(h.x), g1 = __bfloat162float(h.y);
        __nv_bfloat162 l = __float22bfloat162_rn(make_float2(v[2*j]-g0, v[2*j+1]-g1));
        hi[j] = *(uint32_t*)&h; lo[j] = *(uint32_t*)&l;
    }
}

// swizzled byte offset within an 8KB plane for (row, c16)
static __device__ __forceinline__ uint32_t swz(int r, int c) {
    return (uint32_t)(r * 64 + ((c ^ ((r >> 1) & 3)) << 4));
}

// ---------------- pack: fp32 -> bf16 hi/lo swizzled 128x32 tiles ----------------
__global__ void pack_tiles(const float* __restrict__ src, uint8_t* __restrict__ dst,
                           int K, int nslab, int Nreal, int nChunks)
{
    for (int id = blockIdx.x * blockDim.x + threadIdx.x; id < nChunks;
         id += gridDim.x * blockDim.x) {
        const int tile = id >> 9;
        const int w = id & 511;
        const int r = w >> 2, c = w & 3;
        const int mt = tile / nslab;
        const int s  = tile - mt * nslab;
        const int row = mt * 128 + r;
        float v[8] = {0.f,0.f,0.f,0.f,0.f,0.f,0.f,0.f};
        if (row < Nreal) {
            const float* p = src + (size_t)row * K + s * 32 + c * 8;
            *(float4*)&v[0] = *(const float4*)p;
            *(float4*)&v[4] = *(const float4*)(p + 4);
        }
        uint32_t hi[4], lo[4];
        cvt8u(v, hi, lo);
        uint8_t* base = dst + (size_t)tile * 16384 + swz(r, c);
        *(uint4*)base           = *(uint4*)hi;
        *(uint4*)(base + 8192)  = *(uint4*)lo;
    }
}

// ---------------- fused silu(gate)*up -> packed A tiles for down GEMM ----------------
__global__ void pack_silu(const float* __restrict__ guf, uint8_t* __restrict__ dst,
                          int nChunks)
{
    for (int id = blockIdx.x * blockDim.x + threadIdx.x; id < nChunks;
         id += gridDim.x * blockDim.x) {
        const int tile = id >> 9;
        const int w = id & 511;
        const int r = w >> 2, c = w & 3;
        const int mt = tile / 172;
        const int s  = tile - mt * 172;
        const int row = mt * 128 + r;
        const float* p = guf + (size_t)row * 11008 + s * 32 + c * 8;
        float vg[8], vu[8], v[8];
        *(float4*)&vg[0] = *(const float4*)p;
        *(float4*)&vg[4] = *(const float4*)(p + 4);
        *(float4*)&vu[0] = *(const float4*)(p + INTERSZ);
        *(float4*)&vu[4] = *(const float4*)(p + INTERSZ + 4);
#pragma unroll
        for (int j = 0; j < 8; j++)
            v[j] = vu[j] * vg[j] / (1.f + expf(-vg[j]));
        uint32_t hi[4], lo[4];
        cvt8u(v, hi, lo);
        uint8_t* base = dst + (size_t)tile * 16384 + swz(r, c);
        *(uint4*)base           = *(uint4*)hi;
        *(uint4*)(base + 8192)  = *(uint4*)lo;
    }
}

// ====== bf16x3 GEMM, swizzled packed operands, 3-stage K32 cp.async ======
// stage: Ahi(8192) Alo(8192) Bhi(8192) Blo(8192) = 32768 B; 3 stages = 96 KB.
#define OFF_AL 8192
#define OFF_BH 16384
#define OFF_BL 24576
#define STG    32768
#define GSMEM  (3*STG)

__global__ __launch_bounds__(256, 2) void gemm_mma(
    const uint8_t* __restrict__ Ap, const uint8_t* __restrict__ Bp,
    float* __restrict__ C, const float* __restrict__ addv,
    int N, int nslab, int addflag)
{
    extern __shared__ char sm[];
    const int tid  = threadIdx.x;
    const int warp = tid >> 5, lane = tid & 31;
    const int wm = warp >> 2, wn = warp & 3;       // 2 x 4 warps, warp tile 64x32
    const uint32_t sbase = smem_u32(sm);

    const uint8_t* aT = Ap + (size_t)blockIdx.x * nslab * 16384;
    const uint8_t* bT = Bp + (size_t)blockIdx.y * nslab * 16384;

    float acc[4][4][4];
#pragma unroll
    for (int i = 0; i < 4; i++)
#pragma unroll
        for (int j = 0; j < 4; j++)
#pragma unroll
            for (int r = 0; r < 4; r++) acc[i][j][r] = 0.f;

    // prologue: stages 0 and 1 (one commit group each, in order)
#pragma unroll
    for (int ss = 0; ss < 2; ss++) {
        const uint32_t d = sbase + (uint32_t)ss * STG;
        const size_t o = (size_t)ss * 16384;
#pragma unroll
        for (int j = 0; j < 4; j++) {
            const uint32_t cid = (uint32_t)tid * 16 + (uint32_t)j * 4096;
            CPASYNC16(d + cid,         aT + o + cid);
            CPASYNC16(d + 16384 + cid, bT + o + cid);
        }
        asm volatile("cp.async.commit_group;" ::: "memory");
    }

    const int lrow  = lane & 15;
    const int lcsel = lane >> 4;        // 0 or 1 -> 16B column unit within K16

    int cur = 0;                        // s % 3
    for (int s = 0; s < nslab; s++) {
        if (s + 1 < nslab) { asm volatile("cp.async.wait_group 1;" ::: "memory"); }
        else               { asm volatile("cp.async.wait_group 0;" ::: "memory"); }
        __syncthreads();

        if (s + 2 < nslab) {
            int nx2 = cur + 2; if (nx2 >= 3) nx2 -= 3;
            const uint32_t d = sbase + (uint32_t)nx2 * STG;
            const size_t o = (size_t)(s + 2) * 16384;
#pragma unroll
            for (int j = 0; j < 4; j++) {
                const uint32_t cid = (uint32_t)tid * 16 + (uint32_t)j * 4096;
                CPASYNC16(d + cid,         aT + o + cid);
                CPASYNC16(d + 16384 + cid, bT + o + cid);
            }
            asm volatile("cp.async.commit_group;" ::: "memory");
        }

        const uint32_t stb = sbase + (uint32_t)cur * STG;
#pragma unroll
        for (int ks = 0; ks < 2; ks++) {
            const int kc = ks * 2 + lcsel;
            uint32_t bh[2][4], bl[2][4];
#pragma unroll
            for (int bt = 0; bt < 2; bt++) {
                const uint32_t off = swz(wn*32 + bt*16 + lrow, kc);
                LDSM_X4(bh[bt], stb + OFF_BH + off);
                LDSM_X4(bl[bt], stb + OFF_BL + off);
            }
#pragma unroll
            for (int mt = 0; mt < 4; mt++) {
                uint32_t ah[4], al[4];
                const uint32_t off = swz(wm*64 + mt*16 + lrow, kc);
                LDSM_X4(ah, stb + off);
                LDSM_X4(al, stb + OFF_AL + off);
#pragma unroll
                for (int nt = 0; nt < 4; nt++) {
                    const int bt = nt >> 1, sel = nt & 1;
                    const uint32_t b0h = bh[bt][sel], b1h = bh[bt][2+sel];
                    const uint32_t b0l = bl[bt][sel], b1l = bl[bt][2+sel];
                    MMA16816(acc[mt][nt], ah, b0h, b1h);
                    MMA16816(acc[mt][nt], al, b0h, b1h);
                    MMA16816(acc[mt][nt], ah, b0l, b1l);
                }
            }
        }
        if (++cur == 3) cur = 0;
    }

    // ---- epilogue ----
    const int g  = lane >> 2;
    const int t4 = lane & 3;
    const int bm = blockIdx.x * 128, bn = blockIdx.y * 128;
#pragma unroll
    for (int mt = 0; mt < 4; mt++) {
        const int row = bm + wm*64 + mt*16 + g;
#pragma unroll
        for (int nt = 0; nt < 4; nt++) {
            const int col = bn + wn*32 + nt*8 + t4*2;
            if (col < N) {
                float2 v0 = make_float2(acc[mt][nt][0], acc[mt][nt][1]);
                float2 v1 = make_float2(acc[mt][nt][2], acc[mt][nt][3]);
                const size_t i0 = (size_t)row * N + col;
                const size_t i1 = (size_t)(row + 8) * N + col;
                if (addflag) {
                    const float2 a0 = *(const float2*)(addv + i0);
                    const float2 a1 = *(const float2*)(addv + i1);
                    v0.x += a0.x; v0.y += a0.y; v1.x += a1.x; v1.y += a1.y;
                }
                *(float2*)(C + i0) = v0;
                *(float2*)(C + i1) = v1;
            }
        }
    }
}

// ---------------- RMSNorm (optionally * mask) ----------------
__global__ void rmsnorm_kernel(const float* __restrict__ x,
                               const float* __restrict__ w,
                               const float* __restrict__ mask,
                               float* __restrict__ out)
{
    const int m = blockIdx.x;
    const float* row = x + (size_t)m * DMODEL;
    float s = 0.f;
    for (int i = threadIdx.x; i < DMODEL; i += 256) { float v = row[i]; s += v * v; }
#pragma unroll
    for (int o = 16; o > 0; o >>= 1) s += __shfl_xor_sync(0xffffffffu, s, o);
    __shared__ float red[8];
    const int lane = threadIdx.x & 31, wid = threadIdx.x >> 5;
    if (lane == 0) red[wid] = s;
    __syncthreads();
    if (wid == 0) {
        s = (lane < 8) ? red[lane] : 0.f;
#pragma unroll
        for (int o = 4; o > 0; o >>= 1) s += __shfl_xor_sync(0xffffffffu, s, o);
        if (lane == 0) red[0] = s;
    }
    __syncthreads();
    const float inv = rsqrtf(red[0] * (1.0f / (float)DMODEL) + 1e-6f);
    const float mk = mask ? mask[m] : 1.f;
    for (int i = threadIdx.x; i < DMODEL; i += 256)
        out[(size_t)m * DMODEL + i] = row[i] * inv * w[i] * mk;
}

// ---------------- causal depthwise conv1d ----------------
__global__ void conv_kernel(const float* __restrict__ zx,
                            const float* __restrict__ cw,
                            const float* __restrict__ cb,
                            float* __restrict__ xbc)
{
    const int m = blockIdx.x;
    const int t = m & (SEQ - 1);
    for (int c = threadIdx.x; c < CONVDIM; c += 256) {
        float acc = cb[c];
#pragma unroll
        for (int j = 0; j < DCONV; j++) {
            const int tt = t - (DCONV - 1) + j;
            if (tt >= 0)
                acc += cw[c * DCONV + j] *
                       zx[(size_t)(m - (DCONV - 1) + j) * DPROJ + DINNER + c];
        }
        xbc[(size_t)m * CONVDIM + c] = acc;
    }
}

// ---------------- sequential SSM scan + gating (vectorized smem) ----------------
#define CHK 8
#define SBUF 2064
__global__ __launch_bounds__(256) void scan_kernel(
    const float* __restrict__ xbc, const float* __restrict__ zx,
    const float* __restrict__ Dv, const float* __restrict__ zb,
    float* __restrict__ gated)
{
    const int bh = blockIdx.x;
    const int b = bh >> 5;
    const int h = bh & 31;
    const int tid = threadIdx.x;
    const int p = tid >> 2;
    const int q = tid & 3;
    const int n0 = q << 4;

    __shared__ __align__(16) float sd[2][SBUF];

    int lts[9], loff[9], lkind[9], lsh[9];
    bool lvalid[9];
#pragma unroll
    for (int k = 0; k < 9; k++) {
        const int e = tid + k * 256;
        lvalid[k] = (e < CHK * 257);
        const int tsub = e / 257;
        const int j = e - tsub * 257;
        lts[k] = tsub;
        if (j < 64)        { lkind[k] = 0; loff[k] = h * HEADDIM + j;                     lsh[k] = tsub*64 + j; }
        else if (j < 128)  { lkind[k] = 0; loff[k] = DINNER + h * DSTATE + (j - 64);      lsh[k] = 512 + tsub*64 + (j-64); }
        else if (j < 192)  { lkind[k] = 0; loff[k] = DINNER + NHEADS*DSTATE + h*DSTATE + (j-128); lsh[k] = 1024 + tsub*64 + (j-128); }
        else if (j < 256)  { lkind[k] = 1; loff[k] = h * HEADDIM + (j - 192);             lsh[k] = 1536 + tsub*64 + (j-192); }
        else               { lkind[k] = 2; loff[k] = 2*DINNER + 2*NHEADS*DSTATE + h;      lsh[k] = 2048 + tsub; }
    }
#pragma unroll
    for (int k = 0; k < 9; k++) {
        if (lvalid[k]) {
            const size_t m = (size_t)b * SEQ + lts[k];
            float v;
            if (lkind[k] == 0) v = xbc[m * CONVDIM + loff[k]];
            else               v = zx[m * DPROJ + loff[k]];
            if (lkind[k] == 2) v = 1.f / (1.f + expf(v));
            sd[0][lsh[k]] = v;
        }
    }
    __syncthreads();

    float st[16];
#pragma unroll
    for (int i = 0; i < 16; i++) st[i] = 0.f;
    const float Dh = Dv[h];
    const float zbias = zb[h * HEADDIM + p];

    const int NC = SEQ / CHK;
    for (int c = 0; c < NC; c++) {
        const int cur = c & 1;
        const bool pre = (c + 1 < NC);
        float regv[9];
        if (pre) {
#pragma unroll
            for (int k = 0; k < 9; k++) {
                if (lvalid[k]) {
                    const size_t m = (size_t)b * SEQ + (c + 1) * CHK + lts[k];
                    float v;
                    if (lkind[k] == 0) v = xbc[m * CONVDIM + loff[k]];
                    else               v = zx[m * DPROJ + loff[k]];
                    if (lkind[k] == 2) v = 1.f / (1.f + expf(v));
                    regv[k] = v;
                }
            }
        }
        const float* sb = sd[cur];
#pragma unroll
        for (int tsub = 0; tsub < CHK; tsub++) {
            const float a  = sb[2048 + tsub];
            const float xv = sb[tsub*64 + p];
            const float4* Bp4 = (const float4*)(sb + 512 + tsub*64 + n0);
            const float4* Cp4 = (const float4*)(sb + 1024 + tsub*64 + n0);
            float Bv[16], Cv[16];
            *(float4*)&Bv[0]  = Bp4[0]; *(float4*)&Bv[4]  = Bp4[1];
            *(float4*)&Bv[8]  = Bp4[2]; *(float4*)&Bv[12] = Bp4[3];
            *(float4*)&Cv[0]  = Cp4[0]; *(float4*)&Cv[4]  = Cp4[1];
            *(float4*)&Cv[8]  = Cp4[2]; *(float4*)&Cv[12] = Cp4[3];
            float y = 0.f;
#pragma unroll
            for (int i = 0; i < 16; i++) {
                st[i] = a * st[i] + xv * Bv[i];
                y = fmaf(st[i], Cv[i], y);
            }
            y += __shfl_xor_sync(0xffffffffu, y, 1);
            y += __shfl_xor_sync(0xffffffffu, y, 2);
            if (q == 0) {
                const size_t m = (size_t)b * SEQ + c * CHK + tsub;
                const float zval = sb[1536 + tsub*64 + p] + zbias;
                const float sig = 1.f / (1.f + expf(-zval));
                gated[m * DMODEL + h * HEADDIM + p] = (y + Dh * xv) * (zval * sig);
            }
        }
        if (pre) {
#pragma unroll
            for (int k = 0; k < 9; k++)
                if (lvalid[k]) sd[cur ^ 1][lsh[k]] = regv[k];
        }
        __syncthreads();
    }
}

// ---------------- launcher ----------------
extern "C" void kernel_launch(void* const* d_in, const int* in_sizes, int n_in,
                              void* d_out, int out_size)
{
    (void)in_sizes; (void)n_in; (void)out_size;
    const float* hidden     = (const float*)d_in[0];
    const float* mask       = (const float*)d_in[1];
    const float* in_proj_w  = (const float*)d_in[2];
    const float* conv_w     = (const float*)d_in[3];
    const float* conv_b     = (const float*)d_in[4];
    const float* z_bias     = (const float*)d_in[5];
    const float* Dv         = (const float*)d_in[6];
    const float* out_proj_w = (const float*)d_in[7];
    const float* ln1_w      = (const float*)d_in[8];
    const float* ln2_w      = (const float*)d_in[9];
    const float* gate_w     = (const float*)d_in[10];
    const float* up_w       = (const float*)d_in[11];
    const float* down_w     = (const float*)d_in[12];
    float* out = (float*)d_out;

    float *xnorm, *zx, *xbc, *gated, *res2, *guf;
    uint8_t *pa, *pb;
    cudaGetSymbolAddress((void**)&xnorm, g_xnorm);
    cudaGetSymbolAddress((void**)&zx,    g_zx);
    cudaGetSymbolAddress((void**)&xbc,   g_xbc);
    cudaGetSymbolAddress((void**)&gated, g_gated);
    cudaGetSymbolAddress((void**)&res2,  g_res2);
    cudaGetSymbolAddress((void**)&guf,   g_guf);
    cudaGetSymbolAddress((void**)&pa,    g_pa);
    cudaGetSymbolAddress((void**)&pb,    g_pb);

    cudaFuncSetAttribute(gemm_mma, cudaFuncAttributeMaxDynamicSharedMemorySize, GSMEM);
    const int PKG = 4096;

    // ---- mixer ----
    rmsnorm_kernel<<<MROWS, 256>>>(hidden, ln1_w, mask, xnorm);
    pack_tiles<<<PKG, 256>>>(xnorm, pa, 2048, 64, MROWS, 32*64*512);
    pack_tiles<<<PKG, 256>>>(in_proj_w, pb, 2048, 64, DPROJ, 65*64*512);
    gemm_mma<<<dim3(32, 65), 256, GSMEM>>>(pa, pb, zx, nullptr, DPROJ, 64, 0);

    conv_kernel<<<MROWS, 256>>>(zx, conv_w, conv_b, xbc);
    scan_kernel<<<BATCH * NHEADS, 256>>>(xbc, zx, Dv, z_bias, gated);

    pack_tiles<<<PKG, 256>>>(gated, pa, 2048, 64, MROWS, 32*64*512);
    pack_tiles<<<PKG, 256>>>(out_proj_w, pb, 2048, 64, DMODEL, 16*64*512);
    gemm_mma<<<dim3(32, 16), 256, GSMEM>>>(pa, pb, res2, hidden, DMODEL, 64, 1);

    // ---- MLP ----
    rmsnorm_kernel<<<MROWS, 256>>>(res2, ln2_w, nullptr, xnorm);
    pack_tiles<<<PKG, 256>>>(xnorm, pa, 2048, 64, MROWS, 32*64*512);
    pack_tiles<<<PKG, 256>>>(gate_w, pb, 2048, 64, INTERSZ, 43*64*512);
    pack_tiles<<<PKG, 256>>>(up_w, pb + (size_t)43*64*16384, 2048, 64, INTERSZ, 43*64*512);
    gemm_mma<<<dim3(32, 86), 256, GSMEM>>>(pa, pb, guf, nullptr, 11008, 64, 0);

    pack_silu<<<PKG, 256>>>(guf, pa, 32*172*512);
    pack_tiles<<<PKG, 256>>>(down_w, pb, 5504, 172, DMODEL, 16*172*512);
    gemm_mma<<<dim3(32, 16), 256, GSMEM>>>(pa, pb, out, res2, DMODEL, 172, 1);
}

// round 10
// speedup vs baseline: 1.0699x; 1.0165x over previous
#include <cuda_runtime.h>
#include <cuda_bf16.h>
#include <math.h>
#include <stdint.h>

#define BATCH   2
#define SEQ     2048
#define DMODEL  2048
#define NHEADS  32
#define DSTATE  64
#define HEADDIM 64
#define DCONV   4
#define INTERSZ 5504
#define DINNER  DMODEL
#define CONVDIM (DINNER + 2*NHEADS*DSTATE)              /* 6144 */
#define DPROJ   (2*DINNER + 2*NHEADS*DSTATE + NHEADS)   /* 8224 */
#define MROWS   (BATCH*SEQ)                             /* 4096 */

// ---------------- scratch ----------------
__device__ float g_zx   [(size_t)MROWS * DPROJ];
__device__ float g_xbc  [(size_t)MROWS * CONVDIM];
__device__ float g_gated[(size_t)MROWS * DMODEL];
__device__ float g_res2 [(size_t)MROWS * DMODEL];
__device__ float g_guf  [(size_t)MROWS * 11008];
// packed bf16 hi/lo tile images: tile = 128 rows x 32 cols, 64B rows, XOR swizzle.
// hi plane 8192B + lo plane 8192B = 16384B per tile.
// pa: activations (max 32*172 tiles for silu input). pb: all weights resident
// simultaneously (multi-stream overlap): I(65*64) O(16*64) G(43*64) U(43*64) D(16*172).
#define PB_I 0
#define PB_O (65*64)
#define PB_G (PB_O + 16*64)
#define PB_U (PB_G + 43*64)
#define PB_D (PB_U + 43*64)
#define PB_TILES (PB_D + 16*172)
__device__ __align__(128) uint8_t g_pa[(size_t)32 * 172 * 16384];     /* 90 MB  */
__device__ __align__(128) uint8_t g_pb[(size_t)PB_TILES * 16384];     /* 220 MB */

static __device__ __forceinline__ uint32_t smem_u32(const void* p) {
    uint32_t a;
    asm("{ .reg .u64 t; cvta.to.shared.u64 t, %1; cvt.u32.u64 %0, t; }" : "=r"(a) : "l"(p));
    return a;
}

#define LDSM_X4(r, addr) \
    asm volatile("ldmatrix.sync.aligned.m8n8.x4.shared.b16 {%0,%1,%2,%3}, [%4];" \
        : "=r"((r)[0]), "=r"((r)[1]), "=r"((r)[2]), "=r"((r)[3]) : "r"(addr))

#define MMA16816(c, a, b0, b1) \
    asm volatile("mma.sync.aligned.m16n8k16.row.col.f32.bf16.bf16.f32 " \
        "{%0,%1,%2,%3}, {%4,%5,%6,%7}, {%8,%9}, {%0,%1,%2,%3};" \
        : "+f"((c)[0]), "+f"((c)[1]), "+f"((c)[2]), "+f"((c)[3]) \
        : "r"((a)[0]), "r"((a)[1]), "r"((a)[2]), "r"((a)[3]), "r"(b0), "r"(b1))

#define CPASYNC16(dst, src) \
    asm volatile("cp.async.cg.shared.global [%0], [%1], 16;" :: "r"(dst), "l"(src))

static __device__ __forceinline__ void cvt8u(const float* v, uint32_t* hi, uint32_t* lo) {
#pragma unroll
    for (int j = 0; j < 4; j++) {
        __nv_bfloat162 h = __float22bfloat162_rn(make_float2(v[2*j], v[2*j+1]));
        float g0 = __bfloat162float(h.x), g1 = __bfloat162float(h.y);
        __nv_bfloat162 l = __float22bfloat162_rn(make_float2(v[2*j]-g0, v[2*j+1]-g1));
        hi[j] = *(uint32_t*)&h; lo[j] = *(uint32_t*)&l;
    }
}

// swizzled byte offset within an 8KB plane for (row, c16)
static __device__ __forceinline__ uint32_t swz(int r, int c) {
    return (uint32_t)(r * 64 + ((c ^ ((r >> 1) & 3)) << 4));
}

// ---------------- pack: fp32 -> bf16 hi/lo swizzled 128x32 tiles ----------------
__global__ void pack_tiles(const float* __restrict__ src, uint8_t* __restrict__ dst,
                           int K, int nslab, int Nreal, int nChunks)
{
    for (int id = blockIdx.x * blockDim.x + threadIdx.x; id < nChunks;
         id += gridDim.x * blockDim.x) {
        const int tile = id >> 9;
        const int w = id & 511;
        const int r = w >> 2, c = w & 3;
        const int mt = tile / nslab;
        const int s  = tile - mt * nslab;
        const int row = mt * 128 + r;
        float v[8] = {0.f,0.f,0.f,0.f,0.f,0.f,0.f,0.f};
        if (row < Nreal) {
            const float* p = src + (size_t)row * K + s * 32 + c * 8;
            *(float4*)&v[0] = *(const float4*)p;
            *(float4*)&v[4] = *(const float4*)(p + 4);
        }
        uint32_t hi[4], lo[4];
        cvt8u(v, hi, lo);
        uint8_t* base = dst + (size_t)tile * 16384 + swz(r, c);
        *(uint4*)base           = *(uint4*)hi;
        *(uint4*)(base + 8192)  = *(uint4*)lo;
    }
}

// ---------------- fused silu(gate)*up -> packed A tiles for down GEMM ----------------
__global__ void pack_silu(const float* __restrict__ guf, uint8_t* __restrict__ dst,
                          int nChunks)
{
    for (int id = blockIdx.x * blockDim.x + threadIdx.x; id < nChunks;
         id += gridDim.x * blockDim.x) {
        const int tile = id >> 9;
        const int w = id & 511;
        const int r = w >> 2, c = w & 3;
        const int mt = tile / 172;
        const int s  = tile - mt * 172;
        const int row = mt * 128 + r;
        const float* p = guf + (size_t)row * 11008 + s * 32 + c * 8;
        float vg[8], vu[8], v[8];
        *(float4*)&vg[0] = *(const float4*)p;
        *(float4*)&vg[4] = *(const float4*)(p + 4);
        *(float4*)&vu[0] = *(const float4*)(p + INTERSZ);
        *(float4*)&vu[4] = *(const float4*)(p + INTERSZ + 4);
#pragma unroll
        for (int j = 0; j < 8; j++)
            v[j] = vu[j] * vg[j] / (1.f + expf(-vg[j]));
        uint32_t hi[4], lo[4];
        cvt8u(v, hi, lo);
        uint8_t* base = dst + (size_t)tile * 16384 + swz(r, c);
        *(uint4*)base           = *(uint4*)hi;
        *(uint4*)(base + 8192)  = *(uint4*)lo;
    }
}

// ---------------- fused RMSNorm (optionally * mask) -> packed A tiles ----------------
// one block per row; thread t handles cols 8t..8t+7. nslab fixed = 64 (K=2048).
__global__ __launch_bounds__(256) void rmsnorm_pack(const float* __restrict__ x,
                                                    const float* __restrict__ w,
                                                    const float* __restrict__ mask,
                                                    uint8_t* __restrict__ dst)
{
    const int m = blockIdx.x;
    const int t = threadIdx.x;
    const float* row = x + (size_t)m * DMODEL;
    float v[8];
    *(float4*)&v[0] = *(const float4*)(row + t * 8);
    *(float4*)&v[4] = *(const float4*)(row + t * 8 + 4);
    float s = 0.f;
#pragma unroll
    for (int j = 0; j < 8; j++) s += v[j] * v[j];
#pragma unroll
    for (int o = 16; o > 0; o >>= 1) s += __shfl_xor_sync(0xffffffffu, s, o);
    __shared__ float red[8];
    const int lane = t & 31, wid = t >> 5;
    if (lane == 0) red[wid] = s;
    __syncthreads();
    if (wid == 0) {
        s = (lane < 8) ? red[lane] : 0.f;
#pragma unroll
        for (int o = 4; o > 0; o >>= 1) s += __shfl_xor_sync(0xffffffffu, s, o);
        if (lane == 0) red[0] = s;
    }
    __syncthreads();
    const float inv = rsqrtf(red[0] * (1.0f / (float)DMODEL) + 1e-6f) *
                      (mask ? mask[m] : 1.f);
    float wv[8];
    *(float4*)&wv[0] = *(const float4*)(w + t * 8);
    *(float4*)&wv[4] = *(const float4*)(w + t * 8 + 4);
#pragma unroll
    for (int j = 0; j < 8; j++) v[j] = v[j] * inv * wv[j];
    uint32_t hi[4], lo[4];
    cvt8u(v, hi, lo);
    const int st = t >> 2, c = t & 3, r = m & 127;
    uint8_t* base = dst + (size_t)((m >> 7) * 64 + st) * 16384 + swz(r, c);
    *(uint4*)base          = *(uint4*)hi;
    *(uint4*)(base + 8192) = *(uint4*)lo;
}

// ====== bf16x3 GEMM, swizzled packed operands, 3-stage K32 cp.async ======
#define OFF_AL 8192
#define OFF_BH 16384
#define OFF_BL 24576
#define STG    32768
#define GSMEM  (3*STG)

__global__ __launch_bounds__(256, 2) void gemm_mma(
    const uint8_t* __restrict__ Ap, const uint8_t* __restrict__ Bp,
    float* __restrict__ C, const float* __restrict__ addv,
    int N, int nslab, int addflag)
{
    extern __shared__ char sm[];
    const int tid  = threadIdx.x;
    const int warp = tid >> 5, lane = tid & 31;
    const int wm = warp >> 2, wn = warp & 3;       // 2 x 4 warps, warp tile 64x32
    const uint32_t sbase = smem_u32(sm);

    const uint8_t* aT = Ap + (size_t)blockIdx.x * nslab * 16384;
    const uint8_t* bT = Bp + (size_t)blockIdx.y * nslab * 16384;

    float acc[4][4][4];
#pragma unroll
    for (int i = 0; i < 4; i++)
#pragma unroll
        for (int j = 0; j < 4; j++)
#pragma unroll
            for (int r = 0; r < 4; r++) acc[i][j][r] = 0.f;

    // prologue: stages 0 and 1
#pragma unroll
    for (int ss = 0; ss < 2; ss++) {
        const uint32_t d = sbase + (uint32_t)ss * STG;
        const size_t o = (size_t)ss * 16384;
#pragma unroll
        for (int j = 0; j < 4; j++) {
            const uint32_t cid = (uint32_t)tid * 16 + (uint32_t)j * 4096;
            CPASYNC16(d + cid,         aT + o + cid);
            CPASYNC16(d + 16384 + cid, bT + o + cid);
        }
        asm volatile("cp.async.commit_group;" ::: "memory");
    }

    const int lrow  = lane & 15;
    const int lcsel = lane >> 4;

    int cur = 0;
    for (int s = 0; s < nslab; s++) {
        if (s + 1 < nslab) { asm volatile("cp.async.wait_group 1;" ::: "memory"); }
        else               { asm volatile("cp.async.wait_group 0;" ::: "memory"); }
        __syncthreads();

        if (s + 2 < nslab) {
            int nx2 = cur + 2; if (nx2 >= 3) nx2 -= 3;
            const uint32_t d = sbase + (uint32_t)nx2 * STG;
            const size_t o = (size_t)(s + 2) * 16384;
#pragma unroll
            for (int j = 0; j < 4; j++) {
                const uint32_t cid = (uint32_t)tid * 16 + (uint32_t)j * 4096;
                CPASYNC16(d + cid,         aT + o + cid);
                CPASYNC16(d + 16384 + cid, bT + o + cid);
            }
            asm volatile("cp.async.commit_group;" ::: "memory");
        }

        const uint32_t stb = sbase + (uint32_t)cur * STG;
#pragma unroll
        for (int ks = 0; ks < 2; ks++) {
            const int kc = ks * 2 + lcsel;
            uint32_t bh[2][4], bl[2][4];
#pragma unroll
            for (int bt = 0; bt < 2; bt++) {
                const uint32_t off = swz(wn*32 + bt*16 + lrow, kc);
                LDSM_X4(bh[bt], stb + OFF_BH + off);
                LDSM_X4(bl[bt], stb + OFF_BL + off);
            }
#pragma unroll
            for (int mt = 0; mt < 4; mt++) {
                uint32_t ah[4], al[4];
                const uint32_t off = swz(wm*64 + mt*16 + lrow, kc);
                LDSM_X4(ah, stb + off);
                LDSM_X4(al, stb + OFF_AL + off);
#pragma unroll
                for (int nt = 0; nt < 4; nt++) {
                    const int bt = nt >> 1, sel = nt & 1;
                    const uint32_t b0h = bh[bt][sel], b1h = bh[bt][2+sel];
                    const uint32_t b0l = bl[bt][sel], b1l = bl[bt][2+sel];
                    MMA16816(acc[mt][nt], ah, b0h, b1h);
                    MMA16816(acc[mt][nt], al, b0h, b1h);
                    MMA16816(acc[mt][nt], ah, b0l, b1l);
                }
            }
        }
        if (++cur == 3) cur = 0;
    }

    // ---- epilogue ----
    const int g  = lane >> 2;
    const int t4 = lane & 3;
    const int bm = blockIdx.x * 128, bn = blockIdx.y * 128;
#pragma unroll
    for (int mt = 0; mt < 4; mt++) {
        const int row = bm + wm*64 + mt*16 + g;
#pragma unroll
        for (int nt = 0; nt < 4; nt++) {
            const int col = bn + wn*32 + nt*8 + t4*2;
            if (col < N) {
                float2 v0 = make_float2(acc[mt][nt][0], acc[mt][nt][1]);
                float2 v1 = make_float2(acc[mt][nt][2], acc[mt][nt][3]);
                const size_t i0 = (size_t)row * N + col;
                const size_t i1 = (size_t)(row + 8) * N + col;
                if (addflag) {
                    const float2 a0 = *(const float2*)(addv + i0);
                    const float2 a1 = *(const float2*)(addv + i1);
                    v0.x += a0.x; v0.y += a0.y; v1.x += a1.x; v1.y += a1.y;
                }
                *(float2*)(C + i0) = v0;
                *(float2*)(C + i1) = v1;
            }
        }
    }
}

// ---------------- causal depthwise conv1d ----------------
__global__ void conv_kernel(const float* __restrict__ zx,
                            const float* __restrict__ cw,
                            const float* __restrict__ cb,
                            float* __restrict__ xbc)
{
    const int m = blockIdx.x;
    const int t = m & (SEQ - 1);
    for (int c = threadIdx.x; c < CONVDIM; c += 256) {
        float acc = cb[c];
#pragma unroll
        for (int j = 0; j < DCONV; j++) {
            const int tt = t - (DCONV - 1) + j;
            if (tt >= 0)
                acc += cw[c * DCONV + j] *
                       zx[(size_t)(m - (DCONV - 1) + j) * DPROJ + DINNER + c];
        }
        xbc[(size_t)m * CONVDIM + c] = acc;
    }
}

// ---------------- sequential SSM scan + gating (vectorized smem) ----------------
#define CHK 8
#define SBUF 2064
__global__ __launch_bounds__(256) void scan_kernel(
    const float* __restrict__ xbc, const float* __restrict__ zx,
    const float* __restrict__ Dv, const float* __restrict__ zb,
    float* __restrict__ gated)
{
    const int bh = blockIdx.x;
    const int b = bh >> 5;
    const int h = bh & 31;
    const int tid = threadIdx.x;
    const int p = tid >> 2;
    const int q = tid & 3;
    const int n0 = q << 4;

    __shared__ __align__(16) float sd[2][SBUF];

    int lts[9], loff[9], lkind[9], lsh[9];
    bool lvalid[9];
#pragma unroll
    for (int k = 0; k < 9; k++) {
        const int e = tid + k * 256;
        lvalid[k] = (e < CHK * 257);
        const int tsub = e / 257;
        const int j = e - tsub * 257;
        lts[k] = tsub;
        if (j < 64)        { lkind[k] = 0; loff[k] = h * HEADDIM + j;                     lsh[k] = tsub*64 + j; }
        else if (j < 128)  { lkind[k] = 0; loff[k] = DINNER + h * DSTATE + (j - 64);      lsh[k] = 512 + tsub*64 + (j-64); }
        else if (j < 192)  { lkind[k] = 0; loff[k] = DINNER + NHEADS*DSTATE + h*DSTATE + (j-128); lsh[k] = 1024 + tsub*64 + (j-128); }
        else if (j < 256)  { lkind[k] = 1; loff[k] = h * HEADDIM + (j - 192);             lsh[k] = 1536 + tsub*64 + (j-192); }
        else               { lkind[k] = 2; loff[k] = 2*DINNER + 2*NHEADS*DSTATE + h;      lsh[k] = 2048 + tsub; }
    }
#pragma unroll
    for (int k = 0; k < 9; k++) {
        if (lvalid[k]) {
            const size_t m = (size_t)b * SEQ + lts[k];
            float v;
            if (lkind[k] == 0) v = xbc[m * CONVDIM + loff[k]];
            else               v = zx[m * DPROJ + loff[k]];
            if (lkind[k] == 2) v = 1.f / (1.f + expf(v));
            sd[0][lsh[k]] = v;
        }
    }
    __syncthreads();

    float st[16];
#pragma unroll
    for (int i = 0; i < 16; i++) st[i] = 0.f;
    const float Dh = Dv[h];
    const float zbias = zb[h * HEADDIM + p];

    const int NC = SEQ / CHK;
    for (int c = 0; c < NC; c++) {
        const int cur = c & 1;
        const bool pre = (c + 1 < NC);
        float regv[9];
        if (pre) {
#pragma unroll
            for (int k = 0; k < 9; k++) {
                if (lvalid[k]) {
                    const size_t m = (size_t)b * SEQ + (c + 1) * CHK + lts[k];
                    float v;
                    if (lkind[k] == 0) v = xbc[m * CONVDIM + loff[k]];
                    else               v = zx[m * DPROJ + loff[k]];
                    if (lkind[k] == 2) v = 1.f / (1.f + expf(v));
                    regv[k] = v;
                }
            }
        }
        const float* sb = sd[cur];
#pragma unroll
        for (int tsub = 0; tsub < CHK; tsub++) {
            const float a  = sb[2048 + tsub];
            const float xv = sb[tsub*64 + p];
            const float4* Bp4 = (const float4*)(sb + 512 + tsub*64 + n0);
            const float4* Cp4 = (const float4*)(sb + 1024 + tsub*64 + n0);
            float Bv[16], Cv[16];
            *(float4*)&Bv[0]  = Bp4[0]; *(float4*)&Bv[4]  = Bp4[1];
            *(float4*)&Bv[8]  = Bp4[2]; *(float4*)&Bv[12] = Bp4[3];
            *(float4*)&Cv[0]  = Cp4[0]; *(float4*)&Cv[4]  = Cp4[1];
            *(float4*)&Cv[8]  = Cp4[2]; *(float4*)&Cv[12] = Cp4[3];
            float y = 0.f;
#pragma unroll
            for (int i = 0; i < 16; i++) {
                st[i] = a * st[i] + xv * Bv[i];
                y = fmaf(st[i], Cv[i], y);
            }
            y += __shfl_xor_sync(0xffffffffu, y, 1);
            y += __shfl_xor_sync(0xffffffffu, y, 2);
            if (q == 0) {
                const size_t m = (size_t)b * SEQ + c * CHK + tsub;
                const float zval = sb[1536 + tsub*64 + p] + zbias;
                const float sig = 1.f / (1.f + expf(-zval));
                gated[m * DMODEL + h * HEADDIM + p] = (y + Dh * xv) * (zval * sig);
            }
        }
        if (pre) {
#pragma unroll
            for (int k = 0; k < 9; k++)
                if (lvalid[k]) sd[cur ^ 1][lsh[k]] = regv[k];
        }
        __syncthreads();
    }
}

// ---------------- launcher ----------------
extern "C" void kernel_launch(void* const* d_in, const int* in_sizes, int n_in,
                              void* d_out, int out_size)
{
    (void)in_sizes; (void)n_in; (void)out_size;
    const float* hidden     = (const float*)d_in[0];
    const float* mask       = (const float*)d_in[1];
    const float* in_proj_w  = (const float*)d_in[2];
    const float* conv_w     = (const float*)d_in[3];
    const float* conv_b     = (const float*)d_in[4];
    const float* z_bias     = (const float*)d_in[5];
    const float* Dv         = (const float*)d_in[6];
    const float* out_proj_w = (const float*)d_in[7];
    const float* ln1_w      = (const float*)d_in[8];
    const float* ln2_w      = (const float*)d_in[9];
    const float* gate_w     = (const float*)d_in[10];
    const float* up_w       = (const float*)d_in[11];
    const float* down_w     = (const float*)d_in[12];
    float* out = (float*)d_out;

    float *zx, *xbc, *gated, *res2, *guf;
    uint8_t *pa, *pb;
    cudaGetSymbolAddress((void**)&zx,    g_zx);
    cudaGetSymbolAddress((void**)&xbc,   g_xbc);
    cudaGetSymbolAddress((void**)&gated, g_gated);
    cudaGetSymbolAddress((void**)&res2,  g_res2);
    cudaGetSymbolAddress((void**)&guf,   g_guf);
    cudaGetSymbolAddress((void**)&pa,    g_pa);
    cudaGetSymbolAddress((void**)&pb,    g_pb);

    uint8_t* pbI = pb + (size_t)PB_I * 16384;
    uint8_t* pbO = pb + (size_t)PB_O * 16384;
    uint8_t* pbG = pb + (size_t)PB_G * 16384;
    uint8_t* pbD = pb + (size_t)PB_D * 16384;

    cudaFuncSetAttribute(gemm_mma, cudaFuncAttributeMaxDynamicSharedMemorySize, GSMEM);
    const int PKG = 4096;

    // side stream for weight packs (input-only work, overlapped with main chain)
    cudaStream_t s2;
    cudaStreamCreateWithFlags(&s2, cudaStreamNonBlocking);
    cudaEvent_t evF, evI, evO, evGU, evD;
    cudaEventCreateWithFlags(&evF,  cudaEventDisableTiming);
    cudaEventCreateWithFlags(&evI,  cudaEventDisableTiming);
    cudaEventCreateWithFlags(&evO,  cudaEventDisableTiming);
    cudaEventCreateWithFlags(&evGU, cudaEventDisableTiming);
    cudaEventCreateWithFlags(&evD,  cudaEventDisableTiming);

    cudaEventRecord(evF, 0);
    cudaStreamWaitEvent(s2, evF, 0);
    pack_tiles<<<PKG, 256, 0, s2>>>(in_proj_w, pbI, 2048, 64, DPROJ, 65*64*512);
    cudaEventRecord(evI, s2);
    pack_tiles<<<PKG, 256, 0, s2>>>(out_proj_w, pbO, 2048, 64, DMODEL, 16*64*512);
    cudaEventRecord(evO, s2);
    pack_tiles<<<PKG, 256, 0, s2>>>(gate_w, pbG, 2048, 64, INTERSZ, 43*64*512);
    pack_tiles<<<PKG, 256, 0, s2>>>(up_w, pbG + (size_t)43*64*16384, 2048, 64, INTERSZ, 43*64*512);
    cudaEventRecord(evGU, s2);
    pack_tiles<<<PKG, 256, 0, s2>>>(down_w, pbD, 5504, 172, DMODEL, 16*172*512);
    cudaEventRecord(evD, s2);

    // ---- main chain ----
    rmsnorm_pack<<<MROWS, 256>>>(hidden, ln1_w, mask, pa);
    cudaStreamWaitEvent(0, evI, 0);
    gemm_mma<<<dim3(32, 65), 256, GSMEM>>>(pa, pbI, zx, nullptr, DPROJ, 64, 0);

    conv_kernel<<<MROWS, 256>>>(zx, conv_w, conv_b, xbc);
    scan_kernel<<<BATCH * NHEADS, 256>>>(xbc, zx, Dv, z_bias, gated);

    pack_tiles<<<PKG, 256>>>(gated, pa, 2048, 64, MROWS, 32*64*512);
    cudaStreamWaitEvent(0, evO, 0);
    gemm_mma<<<dim3(32, 16), 256, GSMEM>>>(pa, pbO, res2, hidden, DMODEL, 64, 1);

    // ---- MLP ----
    rmsnorm_pack<<<MROWS, 256>>>(res2, ln2_w, nullptr, pa);
    cudaStreamWaitEvent(0, evGU, 0);
    gemm_mma<<<dim3(32, 86), 256, GSMEM>>>(pa, pbG, guf, nullptr, 11008, 64, 0);

    pack_silu<<<PKG, 256>>>(guf, pa, 32*172*512);
    cudaStreamWaitEvent(0, evD, 0);
    gemm_mma<<<dim3(32, 16), 256, GSMEM>>>(pa, pbD, out, res2, DMODEL, 172, 1);
}